// round 13
// baseline (speedup 1.0000x reference)
#include <cuda_runtime.h>
#include <cstdint>

// Top-4 mean pooling: (512, 2048, 7, 7) fp32 -> 1,048,576 rows of 49 floats,
// out[row] = mean(top4(row)).
//
// R13: WARP-AUTONOMOUS pipelines. No __syncthreads anywhere. Each of the 8
// warps in a block owns a private 4-stage smem ring (16-row tiles, 3,136 B
// per stage) and grid-strides over its own tile stream. Rendezvous is
// warp-scoped only: per-lane cp.async wait_group + __syncwarp (~23cyc,
// no cross-warp coupling) instead of block-wide BAR.SYNC. 16 independent
// DRAM-feeding pipelines per SM -> no lockstep duty-cycle loss (the shared
// 71-73% DRAM plateau of R8/R10/R11/R12).
//
// Per-warp tile: 16 rows, 2 lanes/row. Even lane covers row idx [0,24], odd
// covers [24,48] with overlap slot 0 masked to -inf. Register drain (early
// stage release), sort4 + 7-op FMNMX insert chain, shfl.xor(1) bitonic-split
// pair merge (max-half of A ++ reverse(P) = union's top-4 multiset).
//
// smem: 8 warps * 4 stages * 3,136 B = 100,352 B -> 2 blocks/SM, 16 warps/SM.

#define ROW_LEN 49
#define WROWS 16                                   // rows per warp-tile
#define WARPS 8
#define NTHREADS (WARPS * 32)
#define WTILE_FLOATS (WROWS * ROW_LEN)             // 784
#define WTILE_F4 (WTILE_FLOATS / 4)                // 196
#define STAGES 4
#define WARP_SMEM (STAGES * WTILE_FLOATS)          // floats per warp
#define SMEM_BYTES (WARPS * WARP_SMEM * 4)         // 100,352
#define NBLOCKS 296                                // 148 SMs * 2 blocks

__device__ __forceinline__ void cpa16(float* smem_dst, const float4* gsrc) {
    uint32_t s = (uint32_t)__cvta_generic_to_shared(smem_dst);
    asm volatile("cp.async.cg.shared.global [%0], [%1], 16;" :: "r"(s), "l"(gsrc));
}

// One warp issues the cp.asyncs for one 16-row tile into its own stage.
// Each lane commits its own group (6-7 ops per lane).
__device__ __forceinline__ void warp_issue_tile(const float* __restrict__ in,
                                                float* dst, int t, int ntiles,
                                                int lane) {
    if (t < ntiles) {
        const float4* src = reinterpret_cast<const float4*>(in + (size_t)t * WTILE_FLOATS);
        #pragma unroll
        for (int i = lane; i < WTILE_F4; i += 32)
            cpa16(dst + 4 * i, src + i);
    }
    asm volatile("cp.async.commit_group;");   // per-thread group; commit even if empty
}

__global__ __launch_bounds__(NTHREADS)
void apool_topk4_warp(const float* __restrict__ in,
                      float* __restrict__ out,
                      int ntiles) {
    extern __shared__ float smem[];
    const int lane = threadIdx.x & 31;
    const int wid = threadIdx.x >> 5;
    float* wbuf = smem + wid * WARP_SMEM;          // this warp's private ring

    const int gw = blockIdx.x * WARPS + wid;       // global pipeline id
    const int pstride = gridDim.x * WARPS;         // total pipelines

    const int myrow = lane >> 1;                   // 0..15
    const int odd = lane & 1;
    const float NEG_INF = __int_as_float(0xff800000);

    int t = gw;
    // Prologue: fill this warp's 4 stages with tiles t .. t+3*pstride.
    #pragma unroll
    for (int s = 0; s < STAGES; s++)
        warp_issue_tile(in, wbuf + s * WTILE_FLOATS, t + s * pstride, ntiles, lane);

    int stage = 0;
    for (; t < ntiles; t += pstride) {
        asm volatile("cp.async.wait_group 3;");    // own oldest group retired
        __syncwarp();                              // lane-mates' data visible

        // ---- Drain this lane's 25 slots into registers ----
        const float* r = &wbuf[stage * WTILE_FLOATS + myrow * ROW_LEN + odd * 24];
        float v[25];
        #pragma unroll
        for (int i = 0; i < 25; i++) v[i] = r[i];

        __syncwarp();                              // all lanes done -> stage free
        // ---- Refill this stage early (overlaps compute) ----
        warp_issue_tile(in, wbuf + stage * WTILE_FLOATS, t + STAGES * pstride,
                        ntiles, lane);

        // ---- Compute from registers ----
        float a = odd ? NEG_INF : v[0];
        float b = v[1], c = v[2], d = v[3];
        float tt;
        #define CE(x, y) { tt = fmaxf(x, y); y = fminf(x, y); x = tt; }
        CE(a, b); CE(c, d); CE(a, c); CE(b, d); CE(b, c);
        #undef CE

        #pragma unroll
        for (int i = 4; i < 25; i++) {
            float w = v[i];
            float na = fmaxf(a, w); w = fminf(a, w); a = na;
            float nb = fmaxf(b, w); w = fminf(b, w); b = nb;
            float nc = fmaxf(c, w); w = fminf(c, w); c = nc;
            d = fmaxf(d, w);
        }

        float pa = __shfl_xor_sync(0xffffffffu, a, 1);
        float pb = __shfl_xor_sync(0xffffffffu, b, 1);
        float pc = __shfl_xor_sync(0xffffffffu, c, 1);
        float pd = __shfl_xor_sync(0xffffffffu, d, 1);
        float res = (fmaxf(a, pd) + fmaxf(b, pc) + fmaxf(c, pb) + fmaxf(d, pa)) * 0.25f;

        if (!odd) out[t * WROWS + myrow] = res;    // even lanes: consecutive rows

        stage = (stage + 1) & (STAGES - 1);
    }
}

// Tail rows (nrows % WROWS != 0) — not hit for this shape.
__global__ void apool_topk4_tail(const float* __restrict__ in,
                                 float* __restrict__ out,
                                 int row0, int nrows) {
    const int row = row0 + blockIdx.x * blockDim.x + threadIdx.x;
    if (row >= nrows) return;
    const float* r = in + (size_t)row * ROW_LEN;
    float a = r[0], b = r[1], c = r[2], d = r[3];
    float tt;
    #define CE(x, y) { tt = fmaxf(x, y); y = fminf(x, y); x = tt; }
    CE(a, b); CE(c, d); CE(a, c); CE(b, d); CE(b, c);
    #undef CE
    for (int i = 4; i < ROW_LEN; i++) {
        float v = r[i];
        float na = fmaxf(a, v); v = fminf(a, v); a = na;
        float nb = fmaxf(b, v); v = fminf(b, v); b = nb;
        float nc = fmaxf(c, v); v = fminf(c, v); c = nc;
        d = fmaxf(d, v);
    }
    out[row] = (a + b + c + d) * 0.25f;
}

extern "C" void kernel_launch(void* const* d_in, const int* in_sizes, int n_in,
                              void* d_out, int out_size) {
    const float* in = (const float*)d_in[0];
    float* out = (float*)d_out;
    const int nrows = in_sizes[0] / ROW_LEN;     // 1,048,576
    const int ntiles = nrows / WROWS;            // 65,536 full tiles
    const int rem = nrows - ntiles * WROWS;      // 0 for this shape

    static bool attr_set = false;
    if (!attr_set) {
        cudaFuncSetAttribute(apool_topk4_warp,
                             cudaFuncAttributeMaxDynamicSharedMemorySize,
                             SMEM_BYTES);
        attr_set = true;
    }
    const int npipes = NBLOCKS * WARPS;
    const int grid = (ntiles < npipes) ? (ntiles + WARPS - 1) / WARPS : NBLOCKS;
    if (ntiles > 0)
        apool_topk4_warp<<<grid, NTHREADS, SMEM_BYTES>>>(in, out, ntiles);
    if (rem > 0)
        apool_topk4_tail<<<(rem + 127) / 128, 128>>>(in, out,
                                                     ntiles * WROWS, nrows);
}

// round 16
// speedup vs baseline: 1.0276x; 1.0276x over previous
#include <cuda_runtime.h>
#include <cstdint>

// Top-4 mean pooling: (512, 2048, 7, 7) fp32 -> 1,048,576 rows of 49 floats,
// out[row] = mean(top4(row)).
//
// R14: warp-autonomous pipelines (R13) but tuned for OCCUPANCY. The invariant
// across all prior rounds was 16 warps/SM; the measured plateau (DRAM ~72%,
// issue ~43%, nothing saturated) is a request-arrival-rate limit: 2 tiles *
// 25KB per ~2500cyc iteration = 20 B/cyc/SM = 5.3 TB/s chip-wide — exactly
// the plateau. Fix: 2-stage per-warp rings (6,272 B/warp) -> 50,176 B/block
// -> 4 blocks/SM -> 32 independent warp pipelines per SM, ~2x the aggregate
// request issue rate. Shallow rings are fine: 32 staggered pipes keep the
// SM-level request stream dense even though each pipe individually blocks.
//
// Per-warp tile: 16 rows, 2 lanes/row. Even lane covers row idx [0,24], odd
// covers [24,48] with overlap slot 0 masked to -inf. Register drain (early
// stage release), sort4 + 7-op FMNMX insert chain, shfl.xor(1) bitonic-split
// pair merge (max-half of A ++ reverse(P) = union's top-4 multiset).

#define ROW_LEN 49
#define WROWS 16                                   // rows per warp-tile
#define WARPS 8
#define NTHREADS (WARPS * 32)
#define WTILE_FLOATS (WROWS * ROW_LEN)             // 784
#define WTILE_F4 (WTILE_FLOATS / 4)                // 196
#define STAGES 2
#define WARP_SMEM (STAGES * WTILE_FLOATS)          // floats per warp ring
#define SMEM_BYTES (WARPS * WARP_SMEM * 4)         // 50,176
#define NBLOCKS 592                                // 148 SMs * 4 blocks

__device__ __forceinline__ void cpa16(float* smem_dst, const float4* gsrc) {
    uint32_t s = (uint32_t)__cvta_generic_to_shared(smem_dst);
    asm volatile("cp.async.cg.shared.global [%0], [%1], 16;" :: "r"(s), "l"(gsrc));
}

// One warp issues the cp.asyncs for one 16-row tile into its own stage.
// Each lane commits its own group (6-7 ops per lane).
__device__ __forceinline__ void warp_issue_tile(const float* __restrict__ in,
                                                float* dst, int t, int ntiles,
                                                int lane) {
    if (t < ntiles) {
        const float4* src = reinterpret_cast<const float4*>(in + (size_t)t * WTILE_FLOATS);
        #pragma unroll
        for (int i = lane; i < WTILE_F4; i += 32)
            cpa16(dst + 4 * i, src + i);
    }
    asm volatile("cp.async.commit_group;");   // per-thread group; commit even if empty
}

__global__ __launch_bounds__(NTHREADS)
void apool_topk4_occ(const float* __restrict__ in,
                     float* __restrict__ out,
                     int ntiles) {
    extern __shared__ float smem[];
    const int lane = threadIdx.x & 31;
    const int wid = threadIdx.x >> 5;
    float* wbuf = smem + wid * WARP_SMEM;          // this warp's private ring

    const int gw = blockIdx.x * WARPS + wid;       // global pipeline id
    const int pstride = gridDim.x * WARPS;         // total pipelines

    const int myrow = lane >> 1;                   // 0..15
    const int odd = lane & 1;
    const float NEG_INF = __int_as_float(0xff800000);

    int t = gw;
    // Prologue: fill both stages with tiles t, t+pstride.
    warp_issue_tile(in, wbuf,                t,            ntiles, lane);
    warp_issue_tile(in, wbuf + WTILE_FLOATS, t + pstride,  ntiles, lane);

    int stage = 0;
    for (; t < ntiles; t += pstride) {
        asm volatile("cp.async.wait_group 1;");    // own oldest group retired
        __syncwarp();                              // lane-mates' data visible

        // ---- Drain this lane's 25 slots into registers ----
        const float* r = &wbuf[stage * WTILE_FLOATS + myrow * ROW_LEN + odd * 24];
        float v[25];
        #pragma unroll
        for (int i = 0; i < 25; i++) v[i] = r[i];

        __syncwarp();                              // all lanes done -> stage free
        // ---- Refill this stage early (overlaps compute) ----
        warp_issue_tile(in, wbuf + stage * WTILE_FLOATS, t + STAGES * pstride,
                        ntiles, lane);

        // ---- Compute from registers ----
        float a = odd ? NEG_INF : v[0];
        float b = v[1], c = v[2], d = v[3];
        float tt;
        #define CE(x, y) { tt = fmaxf(x, y); y = fminf(x, y); x = tt; }
        CE(a, b); CE(c, d); CE(a, c); CE(b, d); CE(b, c);
        #undef CE

        #pragma unroll
        for (int i = 4; i < 25; i++) {
            float w = v[i];
            float na = fmaxf(a, w); w = fminf(a, w); a = na;
            float nb = fmaxf(b, w); w = fminf(b, w); b = nb;
            float nc = fmaxf(c, w); w = fminf(c, w); c = nc;
            d = fmaxf(d, w);
        }

        float pa = __shfl_xor_sync(0xffffffffu, a, 1);
        float pb = __shfl_xor_sync(0xffffffffu, b, 1);
        float pc = __shfl_xor_sync(0xffffffffu, c, 1);
        float pd = __shfl_xor_sync(0xffffffffu, d, 1);
        float res = (fmaxf(a, pd) + fmaxf(b, pc) + fmaxf(c, pb) + fmaxf(d, pa)) * 0.25f;

        if (!odd) out[t * WROWS + myrow] = res;    // even lanes: consecutive rows

        stage ^= 1;
    }
}

// Tail rows (nrows % WROWS != 0) — not hit for this shape.
__global__ void apool_topk4_tail(const float* __restrict__ in,
                                 float* __restrict__ out,
                                 int row0, int nrows) {
    const int row = row0 + blockIdx.x * blockDim.x + threadIdx.x;
    if (row >= nrows) return;
    const float* r = in + (size_t)row * ROW_LEN;
    float a = r[0], b = r[1], c = r[2], d = r[3];
    float tt;
    #define CE(x, y) { tt = fmaxf(x, y); y = fminf(x, y); x = tt; }
    CE(a, b); CE(c, d); CE(a, c); CE(b, d); CE(b, c);
    #undef CE
    for (int i = 4; i < ROW_LEN; i++) {
        float v = r[i];
        float na = fmaxf(a, v); v = fminf(a, v); a = na;
        float nb = fmaxf(b, v); v = fminf(b, v); b = nb;
        float nc = fmaxf(c, v); v = fminf(c, v); c = nc;
        d = fmaxf(d, v);
    }
    out[row] = (a + b + c + d) * 0.25f;
}

extern "C" void kernel_launch(void* const* d_in, const int* in_sizes, int n_in,
                              void* d_out, int out_size) {
    const float* in = (const float*)d_in[0];
    float* out = (float*)d_out;
    const int nrows = in_sizes[0] / ROW_LEN;     // 1,048,576
    const int ntiles = nrows / WROWS;            // 65,536 full tiles
    const int rem = nrows - ntiles * WROWS;      // 0 for this shape

    static bool attr_set = false;
    if (!attr_set) {
        cudaFuncSetAttribute(apool_topk4_occ,
                             cudaFuncAttributeMaxDynamicSharedMemorySize,
                             SMEM_BYTES);
        attr_set = true;
    }
    const int npipes = NBLOCKS * WARPS;
    const int grid = (ntiles < npipes) ? (ntiles + WARPS - 1) / WARPS : NBLOCKS;
    if (ntiles > 0)
        apool_topk4_occ<<<grid, NTHREADS, SMEM_BYTES>>>(in, out, ntiles);
    if (rem > 0)
        apool_topk4_tail<<<(rem + 127) / 128, 128>>>(in, out,
                                                     ntiles * WROWS, nrows);
}